// round 14
// baseline (speedup 1.0000x reference)
#include <cuda_runtime.h>
#include <cuda_fp16.h>
#include <cstdint>

#define BATCH 32
#define TSEQ  512
#define HDIM  1024
#define G4    4096
#define NBLK  128
#define NTHR  256
#define SMEM_DYN  135168      // milstm: U-stage 2x(128x264x2B)
#define SMEM_GEMM 73728       // sgemm: 4 tiles of 128x72 halves

// ---------------- scratch (device globals; no allocation allowed) ----------------
__device__ float g_gx[(size_t)BATCH * TSEQ * G4];    // 256 MB
__device__ float g_gh2[2 * BATCH * G4];              // parity-buffered gh accumulators
__device__ float g_c[BATCH * HDIM];
__device__ __half g_hh[BATCH * HDIM];                // h state fp16 hi
__device__ __half g_hl[BATCH * HDIM];                // h state fp16 lo
__device__ __half g_Uh[2ULL * G4 * HDIM];            // U fp16 hi
__device__ __half g_Ul[2ULL * G4 * HDIM];            // U fp16 lo
__device__ __half g_Wh[2ULL * G4 * HDIM];            // W fp16 hi
__device__ __half g_Wl[2ULL * G4 * HDIM];            // W fp16 lo
__device__ __half g_Ah[(size_t)BATCH * TSEQ * HDIM]; // GEMM A fp16 hi (x or h0)
__device__ __half g_Al[(size_t)BATCH * TSEQ * HDIM]; // GEMM A fp16 lo
__device__ unsigned g_barcnt = 0;
__device__ volatile unsigned g_bargen = 0;

// ---------------- helpers ----------------
__device__ __forceinline__ float sigmoidf_(float x) {
    return 1.0f / (1.0f + __expf(-x));
}
// fast tanh: 1 - 2/(e^{2x}+1); MUFU-based, rel err ~1e-6, saturates correctly
__device__ __forceinline__ float ftanh(float x) {
    float e = __expf(2.0f * x);
    return 1.0f - 2.0f / (e + 1.0f);
}
__device__ __forceinline__ uint32_t smem_u32(const void* p) {
    uint32_t a;
    asm("{ .reg .u64 t; cvta.to.shared.u64 t, %1; cvt.u32.u64 %0, t; }" : "=r"(a) : "l"(p));
    return a;
}
__device__ __forceinline__ void ldmx4(uint32_t* r, uint32_t addr) {
    asm volatile("ldmatrix.sync.aligned.m8n8.x4.shared.b16 {%0,%1,%2,%3}, [%4];"
                 : "=r"(r[0]), "=r"(r[1]), "=r"(r[2]), "=r"(r[3]) : "r"(addr));
}
__device__ __forceinline__ void mma16816(float* c, const uint32_t* a,
                                         uint32_t b0, uint32_t b1) {
    asm volatile(
        "mma.sync.aligned.m16n8k16.row.col.f32.f16.f16.f32 "
        "{%0,%1,%2,%3}, {%4,%5,%6,%7}, {%8,%9}, {%0,%1,%2,%3};"
        : "+f"(c[0]), "+f"(c[1]), "+f"(c[2]), "+f"(c[3])
        : "r"(a[0]), "r"(a[1]), "r"(a[2]), "r"(a[3]), "r"(b0), "r"(b1));
}
__device__ __forceinline__ void cp16(uint32_t dst, const void* src) {
    asm volatile("cp.async.cg.shared.global [%0], [%1], 16;" :: "r"(dst), "l"(src));
}
__device__ __forceinline__ void cp_commit() {
    asm volatile("cp.async.commit_group;" ::: "memory");
}
__device__ __forceinline__ void cp_wait0() {
    asm volatile("cp.async.wait_group 0;" ::: "memory");
}
__device__ __forceinline__ void cp_wait1() {
    asm volatile("cp.async.wait_group 1;" ::: "memory");
}
__device__ __forceinline__ void redadd(float* p, float v) {
    asm volatile("red.global.add.f32 [%0], %1;" :: "l"(p), "f"(v) : "memory");
}

// grid-wide barrier; all NBLK blocks co-resident (1 block/SM by smem usage).
__device__ __forceinline__ void grid_sync() {
    __threadfence();
    __syncthreads();
    if (threadIdx.x == 0) {
        unsigned gen = g_bargen;
        if (atomicAdd(&g_barcnt, 1u) == NBLK - 1u) {
            g_barcnt = 0u;
            __threadfence();
            g_bargen = gen + 1u;
        } else {
            if (g_bargen == gen) {
                while (g_bargen == gen) { __nanosleep(20); }
            }
            __threadfence();
        }
    }
    __syncthreads();
}

// block-wide 2-value sum reduce
__device__ __forceinline__ float2 reduce2(float a, float b) {
    __shared__ float sA[8], sB[8];
    __syncthreads();
    #pragma unroll
    for (int o = 16; o > 0; o >>= 1) {
        a += __shfl_xor_sync(0xFFFFFFFFu, a, o);
        b += __shfl_xor_sync(0xFFFFFFFFu, b, o);
    }
    int wid = threadIdx.x >> 5, lid = threadIdx.x & 31;
    if (lid == 0) { sA[wid] = a; sB[wid] = b; }
    __syncthreads();
    if (threadIdx.x < 32) {
        a = (lid < 8) ? sA[lid] : 0.0f;
        b = (lid < 8) ? sB[lid] : 0.0f;
        #pragma unroll
        for (int o = 4; o > 0; o >>= 1) {
            a += __shfl_xor_sync(0xFFFFFFFFu, a, o);
            b += __shfl_xor_sync(0xFFFFFFFFu, b, o);
        }
        if (lid == 0) { sA[0] = a; sB[0] = b; }
    }
    __syncthreads();
    return make_float2(sA[0], sB[0]);
}

// ---------------- pack kernels: fp32 -> fp16 hi/lo ----------------
__global__ void pack_hilo(const float* __restrict__ src, __half* __restrict__ dh,
                          __half* __restrict__ dl, size_t total) {
    for (size_t i = (size_t)blockIdx.x * blockDim.x + threadIdx.x; i < total;
         i += (size_t)gridDim.x * blockDim.x) {
        float v = src[i];
        __half hi = __float2half_rn(v);
        dh[i] = hi;
        dl[i] = __float2half_rn(v - __half2float(hi));
    }
}

// ---------------- HMMA big GEMM: C[16384,4096] = A @ B^T + bias ----------------
// 3-pass fp16 hi/lo. Tiles 128(m) x 128(n), BK=64, 256 threads, 2 blocks/SM.
__global__ void __launch_bounds__(256, 2) sgemm_hmma(
    const __half* __restrict__ Ah, const __half* __restrict__ Al,
    const __half* __restrict__ Bh, const __half* __restrict__ Bl,
    const float* __restrict__ bias, float* __restrict__ C)
{
    extern __shared__ __half sm[];
    __half* sAh = sm;                // 128 x 72 halves
    __half* sAl = sm + 9216;
    __half* sBh = sm + 18432;
    __half* sBl = sm + 27648;
    uint32_t base = smem_u32(sm);

    const int tid = threadIdx.x, wid = tid >> 5, lane = tid & 31;
    const int n0 = blockIdx.x * 128, m0 = blockIdx.y * 128;

    float acc[16][4] = {};

    const int rowoff = wid * 16 + (lane & 7) + ((lane >> 3) & 1) * 8;
    const int coloff = (lane >> 4) << 3;

    const uint32_t brow = (uint32_t)(((lane >> 4) & 1) * 8 + (lane & 7));
    const uint32_t bkoff = (uint32_t)(((lane >> 3) & 1) * 16);
    const uint32_t lmBh = base + 36864u + brow * 144u + bkoff;   // sBh bytes
    const uint32_t lmBl = base + 55296u + brow * 144u + bkoff;   // sBl bytes

    for (int k0 = 0; k0 < HDIM; k0 += 64) {
        __syncthreads();
        #pragma unroll
        for (int i = 0; i < 4; i++) {
            int e = tid + i * 256;              // 0..1023
            int row = e >> 3, c8 = (e & 7) * 8;
            *reinterpret_cast<uint4*>(&sAh[row * 72 + c8]) =
                *reinterpret_cast<const uint4*>(&Ah[(size_t)(m0 + row) * HDIM + k0 + c8]);
            *reinterpret_cast<uint4*>(&sAl[row * 72 + c8]) =
                *reinterpret_cast<const uint4*>(&Al[(size_t)(m0 + row) * HDIM + k0 + c8]);
            *reinterpret_cast<uint4*>(&sBh[row * 72 + c8]) =
                *reinterpret_cast<const uint4*>(&Bh[(size_t)(n0 + row) * HDIM + k0 + c8]);
            *reinterpret_cast<uint4*>(&sBl[row * 72 + c8]) =
                *reinterpret_cast<const uint4*>(&Bl[(size_t)(n0 + row) * HDIM + k0 + c8]);
        }
        __syncthreads();
        #pragma unroll
        for (int kq = 0; kq < 4; kq++) {
            uint32_t ah[4], al[4];
            uint32_t addr = base + (uint32_t)(rowoff * 72 + kq * 16 + coloff) * 2u;
            ldmx4(ah, addr);
            ldmx4(al, addr + 18432u);
            #pragma unroll
            for (int p = 0; p < 8; p++) {
                uint32_t bh[4], bl[4];
                uint32_t ba = (uint32_t)(p * 16 * 144) + (uint32_t)(kq * 32);
                ldmx4(bh, lmBh + ba);
                ldmx4(bl, lmBl + ba);
                mma16816(acc[2 * p],     ah, bh[0], bh[1]);
                mma16816(acc[2 * p + 1], ah, bh[2], bh[3]);
                mma16816(acc[2 * p],     ah, bl[0], bl[1]);
                mma16816(acc[2 * p + 1], ah, bl[2], bl[3]);
                mma16816(acc[2 * p],     al, bh[0], bh[1]);
                mma16816(acc[2 * p + 1], al, bh[2], bh[3]);
            }
        }
    }

    #pragma unroll
    for (int nt = 0; nt < 16; nt++)
        #pragma unroll
        for (int c = 0; c < 4; c++) {
            int m = m0 + wid * 16 + ((c >> 1) << 3) + (lane >> 2);
            int n = n0 + nt * 8 + ((lane & 3) << 1) + (c & 1);
            C[(size_t)m * G4 + n] = acc[nt][c] + __ldg(bias + n);
        }
}

// ---------------- persistent HMMA recurrent kernel (K-split, REDG) ----------------
// 128 blocks: bid -> (jt = bid&31, ks4 = bid>>5). Block owns j [jt*128,+128),
// K [ks4*256,+256). Phase A accumulates gh via red.global.add into the
// parity buffer g_gh2[t&1]; ks4==3 blocks zero the next-parity buffer.
// h staging is cp.async, pipelined in two K-halves under the MMA loop.
__global__ void __launch_bounds__(NTHR, 1) milstm_mma(
    const float* __restrict__ gx,
    const __half* __restrict__ Uh, const __half* __restrict__ Ul,
    const float* __restrict__ lngw, const float* __restrict__ lngb,
    const float* __restrict__ lncw, const float* __restrict__ lncb,
    float* __restrict__ out, __half* __restrict__ outh, __half* __restrict__ outl)
{
    extern __shared__ char dsm[];
    uint32_t sbase = smem_u32(dsm);
    __half* hsm = reinterpret_cast<__half*>(dsm);
    float* sgx = reinterpret_cast<float*>(dsm + 33792);            // 4096 floats

    const int tid = threadIdx.x, bid = blockIdx.x;
    const int wid = tid >> 5, lane = tid & 31;
    const int jt = bid & 31, ks4 = bid >> 5;
    const int jb = jt * 128, kb = ks4 * 256;

    // ---- stage U slice (128 rows x 256 K, hi+lo) into smem once ----
    #pragma unroll
    for (int i = 0; i < 16; i++) {
        int e = tid + i * NTHR;                 // 0..4095 uint4
        int row = e >> 5, c8 = (e & 31) * 8;
        *reinterpret_cast<uint4*>(&hsm[row * 264 + c8]) =
            *reinterpret_cast<const uint4*>(&Uh[(size_t)(jb + row) * HDIM + kb + c8]);
        *reinterpret_cast<uint4*>(&hsm[33792 + row * 264 + c8]) =
            *reinterpret_cast<const uint4*>(&Ul[(size_t)(jb + row) * HDIM + kb + c8]);
    }
    __syncthreads();

    // ---- preload U A-fragments (hi+lo) ----
    uint32_t afrh[16][4], afrl[16][4];
    {
        int rowoff = wid * 16 + (lane & 7) + ((lane >> 3) & 1) * 8;
        int coloff = (lane >> 4) << 3;
        #pragma unroll
        for (int kq = 0; kq < 16; kq++) {
            uint32_t addr = sbase + (uint32_t)(rowoff * 264 + kq * 16 + coloff) * 2u;
            ldmx4(afrh[kq], addr);
            ldmx4(afrl[kq], addr + 67584u);
        }
    }
    __syncthreads();

    // ---- zero-init recurrent state + both gh parity buffers ----
    {
        int i = bid * NTHR + tid;               // covers 32768 = BATCH*HDIM
        g_c[i] = 0.0f;
        g_hh[i] = __float2half(0.0f);
        g_hl[i] = __float2half(0.0f);
        #pragma unroll
        for (int q = 0; q < 8; q++)
            g_gh2[i + q * 32768] = 0.0f;        // 8*32768 = 2*BATCH*G4
    }
    grid_sync();

    // phase-B per-thread constants
    const int j4 = tid * 4;
    float4 lw[4], lb[4];
    #pragma unroll
    for (int s = 0; s < 4; s++) {
        lw[s] = *(const float4*)(lngw + s * 1024 + j4);
        lb[s] = *(const float4*)(lngb + s * 1024 + j4);
    }
    float4 cw = *(const float4*)(lncw + j4);
    float4 cb = *(const float4*)(lncb + j4);

    // per-lane ldmatrix bases for h B-fragments (2 nt-pairs x hi/lo)
    const uint32_t hrow = (uint32_t)(((lane >> 4) & 1) * 8 + (lane & 7));
    const uint32_t hkoff = (uint32_t)(((lane >> 3) & 1) * 16);
    const uint32_t lmH0 = sbase + hrow * 528u + hkoff;              // pair 0, hi
    const uint32_t lmH1 = sbase + (16u + hrow) * 528u + hkoff;      // pair 1, hi
    const uint32_t lmL0 = lmH0 + 16896u;                            // lo
    const uint32_t lmL1 = lmH1 + 16896u;

    for (int t = 0; t < TSEQ; ++t) {
        // ---- gx prefetch for phase B (own slice only; self-consumed) ----
        if (bid < BATCH) {
            const char* src = (const char*)(gx + ((size_t)bid * TSEQ + t) * G4);
            #pragma unroll
            for (int i = 0; i < 4; i++)
                cp16(sbase + 33792u + (uint32_t)(tid * 16 + i * 4096),
                     src + tid * 16 + i * 4096);
            cp_commit();
        }

        // ---- stage h slice via cp.async, two K-halves ----
        #pragma unroll
        for (int half = 0; half < 2; half++) {
            uint32_t koffB = (uint32_t)(half * 256);        // byte offset within row
            int koffE = half * 128;                          // element offset
            #pragma unroll
            for (int pr = 0; pr < 2; pr++) {
                const __half* src = pr ? g_hl : g_hh;
                uint32_t dbase = sbase + (uint32_t)(pr * 16896);
                #pragma unroll
                for (int i = 0; i < 2; i++) {
                    int e = tid + i * NTHR;                  // 0..511
                    int row = e >> 4, c = e & 15;
                    cp16(dbase + (uint32_t)row * 528u + koffB + (uint32_t)c * 16u,
                         src + row * HDIM + kb + koffE + c * 8);
                }
            }
            cp_commit();
        }

        // ---- zero next-parity gh buffer (ks4==3 blocks; overlaps cp latency) ----
        if (ks4 == 3) {
            int zb = ((t + 1) & 1) * (BATCH * G4);
            float4 z = make_float4(0.0f, 0.0f, 0.0f, 0.0f);
            #pragma unroll
            for (int i = 0; i < 4; i++) {
                int e = tid + i * NTHR;                      // 0..1023
                int r = e >> 5, jl = (e & 31) * 4;
                *(float4*)&g_gh2[zb + r * G4 + jb + jl] = z;
            }
        }

        // ---- 3-pass MMA, pipelined over the two staged halves ----
        float acc[4][4] = {};
        cp_wait1();            // half 0 (and gx where issued) complete
        __syncthreads();
        #pragma unroll
        for (int kq = 0; kq < 8; kq++) {
            uint32_t ka = (uint32_t)(kq * 32);
            uint32_t bh[8], bl[8];
            ldmx4(bh,     lmH0 + ka);
            ldmx4(bh + 4, lmH1 + ka);
            ldmx4(bl,     lmL0 + ka);
            ldmx4(bl + 4, lmL1 + ka);
            #pragma unroll
            for (int nt = 0; nt < 4; nt++)
                mma16816(acc[nt], afrh[kq], bh[2 * nt], bh[2 * nt + 1]);
            #pragma unroll
            for (int nt = 0; nt < 4; nt++)
                mma16816(acc[nt], afrh[kq], bl[2 * nt], bl[2 * nt + 1]);
            #pragma unroll
            for (int nt = 0; nt < 4; nt++)
                mma16816(acc[nt], afrl[kq], bh[2 * nt], bh[2 * nt + 1]);
        }
        cp_wait0();            // half 1 complete
        __syncthreads();
        #pragma unroll
        for (int kq = 8; kq < 16; kq++) {
            uint32_t ka = (uint32_t)(kq * 32);
            uint32_t bh[8], bl[8];
            ldmx4(bh,     lmH0 + ka);
            ldmx4(bh + 4, lmH1 + ka);
            ldmx4(bl,     lmL0 + ka);
            ldmx4(bl + 4, lmL1 + ka);
            #pragma unroll
            for (int nt = 0; nt < 4; nt++)
                mma16816(acc[nt], afrh[kq], bh[2 * nt], bh[2 * nt + 1]);
            #pragma unroll
            for (int nt = 0; nt < 4; nt++)
                mma16816(acc[nt], afrh[kq], bl[2 * nt], bl[2 * nt + 1]);
            #pragma unroll
            for (int nt = 0; nt < 4; nt++)
                mma16816(acc[nt], afrl[kq], bh[2 * nt], bh[2 * nt + 1]);
        }

        // ---- accumulate partials via REDG into parity buffer ----
        {
            int pb = (t & 1) * (BATCH * G4);
            #pragma unroll
            for (int nt = 0; nt < 4; nt++)
                #pragma unroll
                for (int c = 0; c < 4; c++) {
                    int jl = wid * 16 + ((c >> 1) << 3) + (lane >> 2);
                    int r = nt * 8 + ((lane & 3) << 1) + (c & 1);
                    redadd(&g_gh2[pb + r * G4 + jb + jl], acc[nt][c]);
                }
        }
        grid_sync();

        // ---- phase B: blocks 0..31, one batch row each ----
        if (bid < BATCH) {
            const int r = bid;
            const int pb = (t & 1) * (BATCH * G4);
            float v[4][4];
            float s = 0.0f, s2 = 0.0f;
            #pragma unroll
            for (int sec = 0; sec < 4; sec++) {
                float4 gh = *(const float4*)&g_gh2[pb + r * G4 + sec * 1024 + j4];
                float4 xv = *(const float4*)(sgx + sec * 1024 + j4);
                v[sec][0] = xv.x + gh.x + xv.x * gh.x;
                v[sec][1] = xv.y + gh.y + xv.y * gh.y;
                v[sec][2] = xv.z + gh.z + xv.z * gh.z;
                v[sec][3] = xv.w + gh.w + xv.w * gh.w;
                #pragma unroll
                for (int q = 0; q < 4; q++) { s += v[sec][q]; s2 += v[sec][q] * v[sec][q]; }
            }
            float2 tot = reduce2(s, s2);
            float mean = tot.x * (1.0f / G4);
            float var  = tot.y * (1.0f / G4) - mean * mean;
            float rstd = rsqrtf(var + 1e-5f);

            float4 cprev = *(const float4*)(g_c + r * HDIM + j4);
            const float* pcp = &cprev.x;
            float ov[4], cv[4];
            float cs = 0.0f, cs2 = 0.0f;
            #pragma unroll
            for (int q = 0; q < 4; q++) {
                const float* pw0 = &lw[0].x; const float* pb0 = &lb[0].x;
                const float* pw1 = &lw[1].x; const float* pb1 = &lb[1].x;
                const float* pw2 = &lw[2].x; const float* pb2 = &lb[2].x;
                const float* pw3 = &lw[3].x; const float* pb3 = &lb[3].x;
                float gi = (v[0][q] - mean) * rstd * pw0[q] + pb0[q];
                float gf = (v[1][q] - mean) * rstd * pw1[q] + pb1[q];
                float gg = (v[2][q] - mean) * rstd * pw2[q] + pb2[q];
                float go = (v[3][q] - mean) * rstd * pw3[q] + pb3[q];
                float ivv = sigmoidf_(gi);
                float fvv = sigmoidf_(gf);
                float gvv = ftanh(gg);
                ov[q] = sigmoidf_(go);
                float c = fvv * pcp[q] + ivv * gvv;
                cv[q] = c;
                cs += c; cs2 += c * c;
            }
            float2 ct = reduce2(cs, cs2);
            float cm   = ct.x * (1.0f / HDIM);
            float cvar = ct.y * (1.0f / HDIM) - cm * cm;
            float crs  = rsqrtf(cvar + 1e-5f);
            const float* pcw = &cw.x; const float* pcb = &cb.x;
            float4 cno, hno;
            float* pcn = &cno.x; float* phn = &hno.x;
            #pragma unroll
            for (int q = 0; q < 4; q++) {
                float cn = (cv[q] - cm) * crs * pcw[q] + pcb[q];
                pcn[q] = cn;
                phn[q] = ov[q] * ftanh(cn);
            }
            *(float4*)(g_c + r * HDIM + j4) = cno;
            __half hh0 = __float2half_rn(hno.x);
            __half hh1 = __float2half_rn(hno.y);
            __half hh2 = __float2half_rn(hno.z);
            __half hh3 = __float2half_rn(hno.w);
            __half hl0 = __float2half_rn(hno.x - __half2float(hh0));
            __half hl1 = __float2half_rn(hno.y - __half2float(hh1));
            __half hl2 = __float2half_rn(hno.z - __half2float(hh2));
            __half hl3 = __float2half_rn(hno.w - __half2float(hh3));
            *reinterpret_cast<__half2*>(g_hh + r * HDIM + j4)     = __halves2half2(hh0, hh1);
            *reinterpret_cast<__half2*>(g_hh + r * HDIM + j4 + 2) = __halves2half2(hh2, hh3);
            *reinterpret_cast<__half2*>(g_hl + r * HDIM + j4)     = __halves2half2(hl0, hl1);
            *reinterpret_cast<__half2*>(g_hl + r * HDIM + j4 + 2) = __halves2half2(hl2, hl3);
            size_t obase = ((size_t)r * TSEQ + t) * HDIM + j4;
            if (out) {
                *(float4*)(out + obase) = hno;
            } else {
                *reinterpret_cast<__half2*>(outh + obase)     = __halves2half2(hh0, hh1);
                *reinterpret_cast<__half2*>(outh + obase + 2) = __halves2half2(hh2, hh3);
                *reinterpret_cast<__half2*>(outl + obase)     = __halves2half2(hl0, hl1);
                *reinterpret_cast<__half2*>(outl + obase + 2) = __halves2half2(hl2, hl3);
            }
        }
        grid_sync();
    }
}

// ---------------- launch ----------------
extern "C" void kernel_launch(void* const* d_in, const int* in_sizes, int n_in,
                              void* d_out, int out_size) {
    const float* x    = (const float*)d_in[0];
    const float* W    = (const float*)d_in[1];
    const float* b    = (const float*)d_in[2];
    const float* U    = (const float*)d_in[3];
    const float* lngw = (const float*)d_in[4];
    const float* lngb = (const float*)d_in[5];
    const float* lncw = (const float*)d_in[6];
    const float* lncb = (const float*)d_in[7];
    float* y = (float*)d_out;

    cudaFuncSetAttribute(milstm_mma, cudaFuncAttributeMaxDynamicSharedMemorySize,
                         SMEM_DYN);
    cudaFuncSetAttribute(sgemm_hmma, cudaFuncAttributeMaxDynamicSharedMemorySize,
                         SMEM_GEMM);

    float *gx;
    cudaGetSymbolAddress((void**)&gx, g_gx);
    __half *Uh, *Ul, *Wh, *Wl, *Ah, *Al;
    cudaGetSymbolAddress((void**)&Uh, g_Uh);
    cudaGetSymbolAddress((void**)&Ul, g_Ul);
    cudaGetSymbolAddress((void**)&Wh, g_Wh);
    cudaGetSymbolAddress((void**)&Wl, g_Wl);
    cudaGetSymbolAddress((void**)&Ah, g_Ah);
    cudaGetSymbolAddress((void**)&Al, g_Al);

    const size_t WSZ = 2ULL * G4 * HDIM;
    const size_t ASZ = (size_t)BATCH * TSEQ * HDIM;
    const size_t LOFF = (size_t)G4 * HDIM;

    pack_hilo<<<1024, 256>>>(U, Uh, Ul, WSZ);
    pack_hilo<<<1024, 256>>>(W, Wh, Wl, WSZ);
    pack_hilo<<<1024, 256>>>(x, Ah, Al, ASZ);

    dim3 gg(G4 / 128, BATCH * TSEQ / 128);   // (32, 128)

    // layer 0 (h written straight to Ah/Al in sgemm A-layout)
    sgemm_hmma<<<gg, 256, SMEM_GEMM>>>(Ah, Al, Wh, Wl, b, gx);
    milstm_mma<<<NBLK, NTHR, SMEM_DYN>>>(gx, Uh, Ul, lngw, lngb, lncw, lncb,
                                         nullptr, Ah, Al);
    // layer 1
    sgemm_hmma<<<gg, 256, SMEM_GEMM>>>(Ah, Al, Wh + LOFF, Wl + LOFF, b + G4, gx);
    milstm_mma<<<NBLK, NTHR, SMEM_DYN>>>(gx, Uh + LOFF, Ul + LOFF,
                                         lngw + G4, lngb + G4,
                                         lncw + HDIM, lncb + HDIM, y,
                                         nullptr, nullptr);
}

// round 15
// speedup vs baseline: 1.1183x; 1.1183x over previous
#include <cuda_runtime.h>
#include <cuda_fp16.h>
#include <cstdint>

#define BATCH 32
#define TSEQ  512
#define HDIM  1024
#define G4    4096
#define NBLK  128
#define NTHR  256
#define SMEM_DYN  135168      // milstm: U-stage 2x(128x264x2B)
#define SMEM_GEMM 73728       // sgemm: 4 tiles of 128x72 halves

// ---------------- scratch (device globals; no allocation allowed) ----------------
__device__ float g_gx[(size_t)BATCH * TSEQ * G4];    // 256 MB
__device__ float g_ghp[4ULL * BATCH * G4];           // K-split partials, [ks][r][j]
__device__ float g_c[BATCH * HDIM];
__device__ __half g_hh[BATCH * HDIM];                // h state fp16 hi
__device__ __half g_hl[BATCH * HDIM];                // h state fp16 lo
__device__ __half g_Uh[2ULL * G4 * HDIM];            // U fp16 hi
__device__ __half g_Ul[2ULL * G4 * HDIM];            // U fp16 lo
__device__ __half g_Wh[2ULL * G4 * HDIM];            // W fp16 hi
__device__ __half g_Wl[2ULL * G4 * HDIM];            // W fp16 lo
__device__ __half g_Ah[(size_t)BATCH * TSEQ * HDIM]; // GEMM A fp16 hi (x or h0)
__device__ __half g_Al[(size_t)BATCH * TSEQ * HDIM]; // GEMM A fp16 lo
__device__ unsigned g_barcnt = 0;
__device__ volatile unsigned g_bargen = 0;
__device__ unsigned g_cnt_p = 0;   // partial-producer arrivals (128/step)
__device__ unsigned g_cnt_h = 0;   // h-publisher arrivals (32/step)

// ---------------- helpers ----------------
__device__ __forceinline__ float sigmoidf_(float x) {
    return 1.0f / (1.0f + __expf(-x));
}
// fast tanh: 1 - 2/(e^{2x}+1); MUFU-based, rel err ~1e-6, saturates correctly
__device__ __forceinline__ float ftanh(float x) {
    float e = __expf(2.0f * x);
    return 1.0f - 2.0f / (e + 1.0f);
}
__device__ __forceinline__ uint32_t smem_u32(const void* p) {
    uint32_t a;
    asm("{ .reg .u64 t; cvta.to.shared.u64 t, %1; cvt.u32.u64 %0, t; }" : "=r"(a) : "l"(p));
    return a;
}
__device__ __forceinline__ void ldmx4(uint32_t* r, uint32_t addr) {
    asm volatile("ldmatrix.sync.aligned.m8n8.x4.shared.b16 {%0,%1,%2,%3}, [%4];"
                 : "=r"(r[0]), "=r"(r[1]), "=r"(r[2]), "=r"(r[3]) : "r"(addr));
}
__device__ __forceinline__ void mma16816(float* c, const uint32_t* a,
                                         uint32_t b0, uint32_t b1) {
    asm volatile(
        "mma.sync.aligned.m16n8k16.row.col.f32.f16.f16.f32 "
        "{%0,%1,%2,%3}, {%4,%5,%6,%7}, {%8,%9}, {%0,%1,%2,%3};"
        : "+f"(c[0]), "+f"(c[1]), "+f"(c[2]), "+f"(c[3])
        : "r"(a[0]), "r"(a[1]), "r"(a[2]), "r"(a[3]), "r"(b0), "r"(b1));
}
__device__ __forceinline__ void cp16(uint32_t dst, const void* src) {
    asm volatile("cp.async.cg.shared.global [%0], [%1], 16;" :: "r"(dst), "l"(src));
}
__device__ __forceinline__ void cp_commit() {
    asm volatile("cp.async.commit_group;" ::: "memory");
}
__device__ __forceinline__ void cp_wait0() {
    asm volatile("cp.async.wait_group 0;" ::: "memory");
}

// grid-wide barrier; all NBLK blocks co-resident (used once after init)
__device__ __forceinline__ void grid_sync() {
    __threadfence();
    __syncthreads();
    if (threadIdx.x == 0) {
        unsigned gen = g_bargen;
        if (atomicAdd(&g_barcnt, 1u) == NBLK - 1u) {
            g_barcnt = 0u;
            __threadfence();
            g_bargen = gen + 1u;
        } else {
            if (g_bargen == gen) {
                while (g_bargen == gen) { __nanosleep(20); }
            }
            __threadfence();
        }
    }
    __syncthreads();
}

// spin until a monotonic counter reaches target (tid 0), then block-sync
__device__ __forceinline__ void wait_counter(unsigned* cnt, unsigned tgt) {
    if (threadIdx.x == 0) {
        if (*(volatile unsigned*)cnt < tgt) {
            while (*(volatile unsigned*)cnt < tgt) { __nanosleep(20); }
        }
        __threadfence();
    }
    __syncthreads();
}
// publish: all threads fenced+synced, then tid 0 bumps the counter
__device__ __forceinline__ void arrive_counter(unsigned* cnt) {
    __threadfence();
    __syncthreads();
    if (threadIdx.x == 0) atomicAdd(cnt, 1u);
}

// block-wide 2-value sum reduce
__device__ __forceinline__ float2 reduce2(float a, float b) {
    __shared__ float sA[8], sB[8];
    __syncthreads();
    #pragma unroll
    for (int o = 16; o > 0; o >>= 1) {
        a += __shfl_xor_sync(0xFFFFFFFFu, a, o);
        b += __shfl_xor_sync(0xFFFFFFFFu, b, o);
    }
    int wid = threadIdx.x >> 5, lid = threadIdx.x & 31;
    if (lid == 0) { sA[wid] = a; sB[wid] = b; }
    __syncthreads();
    if (threadIdx.x < 32) {
        a = (lid < 8) ? sA[lid] : 0.0f;
        b = (lid < 8) ? sB[lid] : 0.0f;
        #pragma unroll
        for (int o = 4; o > 0; o >>= 1) {
            a += __shfl_xor_sync(0xFFFFFFFFu, a, o);
            b += __shfl_xor_sync(0xFFFFFFFFu, b, o);
        }
        if (lid == 0) { sA[0] = a; sB[0] = b; }
    }
    __syncthreads();
    return make_float2(sA[0], sB[0]);
}

// ---------------- pack kernels: fp32 -> fp16 hi/lo ----------------
__global__ void pack_hilo(const float* __restrict__ src, __half* __restrict__ dh,
                          __half* __restrict__ dl, size_t total) {
    for (size_t i = (size_t)blockIdx.x * blockDim.x + threadIdx.x; i < total;
         i += (size_t)gridDim.x * blockDim.x) {
        float v = src[i];
        __half hi = __float2half_rn(v);
        dh[i] = hi;
        dl[i] = __float2half_rn(v - __half2float(hi));
    }
}

// ---------------- HMMA big GEMM: C[16384,4096] = A @ B^T + bias ----------------
// 3-pass fp16 hi/lo. Tiles 128(m) x 128(n), BK=64, 256 threads, 2 blocks/SM.
__global__ void __launch_bounds__(256, 2) sgemm_hmma(
    const __half* __restrict__ Ah, const __half* __restrict__ Al,
    const __half* __restrict__ Bh, const __half* __restrict__ Bl,
    const float* __restrict__ bias, float* __restrict__ C)
{
    extern __shared__ __half sm[];
    __half* sAh = sm;                // 128 x 72 halves
    __half* sAl = sm + 9216;
    __half* sBh = sm + 18432;
    __half* sBl = sm + 27648;
    uint32_t base = smem_u32(sm);

    const int tid = threadIdx.x, wid = tid >> 5, lane = tid & 31;
    const int n0 = blockIdx.x * 128, m0 = blockIdx.y * 128;

    float acc[16][4] = {};

    const int rowoff = wid * 16 + (lane & 7) + ((lane >> 3) & 1) * 8;
    const int coloff = (lane >> 4) << 3;

    const uint32_t brow = (uint32_t)(((lane >> 4) & 1) * 8 + (lane & 7));
    const uint32_t bkoff = (uint32_t)(((lane >> 3) & 1) * 16);
    const uint32_t lmBh = base + 36864u + brow * 144u + bkoff;   // sBh bytes
    const uint32_t lmBl = base + 55296u + brow * 144u + bkoff;   // sBl bytes

    for (int k0 = 0; k0 < HDIM; k0 += 64) {
        __syncthreads();
        #pragma unroll
        for (int i = 0; i < 4; i++) {
            int e = tid + i * 256;              // 0..1023
            int row = e >> 3, c8 = (e & 7) * 8;
            *reinterpret_cast<uint4*>(&sAh[row * 72 + c8]) =
                *reinterpret_cast<const uint4*>(&Ah[(size_t)(m0 + row) * HDIM + k0 + c8]);
            *reinterpret_cast<uint4*>(&sAl[row * 72 + c8]) =
                *reinterpret_cast<const uint4*>(&Al[(size_t)(m0 + row) * HDIM + k0 + c8]);
            *reinterpret_cast<uint4*>(&sBh[row * 72 + c8]) =
                *reinterpret_cast<const uint4*>(&Bh[(size_t)(n0 + row) * HDIM + k0 + c8]);
            *reinterpret_cast<uint4*>(&sBl[row * 72 + c8]) =
                *reinterpret_cast<const uint4*>(&Bl[(size_t)(n0 + row) * HDIM + k0 + c8]);
        }
        __syncthreads();
        #pragma unroll
        for (int kq = 0; kq < 4; kq++) {
            uint32_t ah[4], al[4];
            uint32_t addr = base + (uint32_t)(rowoff * 72 + kq * 16 + coloff) * 2u;
            ldmx4(ah, addr);
            ldmx4(al, addr + 18432u);
            #pragma unroll
            for (int p = 0; p < 8; p++) {
                uint32_t bh[4], bl[4];
                uint32_t ba = (uint32_t)(p * 16 * 144) + (uint32_t)(kq * 32);
                ldmx4(bh, lmBh + ba);
                ldmx4(bl, lmBl + ba);
                mma16816(acc[2 * p],     ah, bh[0], bh[1]);
                mma16816(acc[2 * p + 1], ah, bh[2], bh[3]);
                mma16816(acc[2 * p],     ah, bl[0], bl[1]);
                mma16816(acc[2 * p + 1], ah, bl[2], bl[3]);
                mma16816(acc[2 * p],     al, bh[0], bh[1]);
                mma16816(acc[2 * p + 1], al, bh[2], bh[3]);
            }
        }
    }

    #pragma unroll
    for (int nt = 0; nt < 16; nt++)
        #pragma unroll
        for (int c = 0; c < 4; c++) {
            int m = m0 + wid * 16 + ((c >> 1) << 3) + (lane >> 2);
            int n = n0 + nt * 8 + ((lane & 3) << 1) + (c & 1);
            C[(size_t)m * G4 + n] = acc[nt][c] + __ldg(bias + n);
        }
}

// ---------------- persistent HMMA recurrent kernel (K-split, counters) -----------
// 128 blocks: bid -> (jt = bid&31, ks4 = bid>>5). Block owns j [jt*128,+128),
// K [ks4*256,+256). Per step:
//   wait cnt_h>=32*t -> stage h -> 3-pass MMA -> store partials -> arrive cnt_p
//   phase-B blocks (bid<32): wait cnt_p>=128*(t+1) -> LN/cell -> publish h
//   -> arrive cnt_h.
// No parity buffers needed: partial overwrites at t+1 are gated by cnt_h
// (phase B finished reading), h overwrites at t+1 gated by cnt_p (staging done).
__global__ void __launch_bounds__(NTHR, 1) milstm_mma(
    const float* __restrict__ gx,
    const __half* __restrict__ Uh, const __half* __restrict__ Ul,
    const float* __restrict__ lngw, const float* __restrict__ lngb,
    const float* __restrict__ lncw, const float* __restrict__ lncb,
    float* __restrict__ out, __half* __restrict__ outh, __half* __restrict__ outl)
{
    extern __shared__ char dsm[];
    uint32_t sbase = smem_u32(dsm);
    __half* hsm = reinterpret_cast<__half*>(dsm);
    float* sgx = reinterpret_cast<float*>(dsm + 33792);            // 4096 floats

    const int tid = threadIdx.x, bid = blockIdx.x;
    const int wid = tid >> 5, lane = tid & 31;
    const int jt = bid & 31, ks4 = bid >> 5;
    const int jb = jt * 128, kb = ks4 * 256;

    // ---- stage U slice (128 rows x 256 K, hi+lo) into smem once ----
    #pragma unroll
    for (int i = 0; i < 16; i++) {
        int e = tid + i * NTHR;                 // 0..4095 uint4
        int row = e >> 5, c8 = (e & 31) * 8;
        *reinterpret_cast<uint4*>(&hsm[row * 264 + c8]) =
            *reinterpret_cast<const uint4*>(&Uh[(size_t)(jb + row) * HDIM + kb + c8]);
        *reinterpret_cast<uint4*>(&hsm[33792 + row * 264 + c8]) =
            *reinterpret_cast<const uint4*>(&Ul[(size_t)(jb + row) * HDIM + kb + c8]);
    }
    __syncthreads();

    // ---- preload U A-fragments (hi+lo) ----
    uint32_t afrh[16][4], afrl[16][4];
    {
        int rowoff = wid * 16 + (lane & 7) + ((lane >> 3) & 1) * 8;
        int coloff = (lane >> 4) << 3;
        #pragma unroll
        for (int kq = 0; kq < 16; kq++) {
            uint32_t addr = sbase + (uint32_t)(rowoff * 264 + kq * 16 + coloff) * 2u;
            ldmx4(afrh[kq], addr);
            ldmx4(afrl[kq], addr + 67584u);
        }
    }
    __syncthreads();

    // ---- zero-init recurrent state + counters ----
    {
        int i = bid * NTHR + tid;               // covers 32768 = BATCH*HDIM
        g_c[i] = 0.0f;
        g_hh[i] = __float2half(0.0f);
        g_hl[i] = __float2half(0.0f);
        if (bid == 0 && tid == 0) { g_cnt_p = 0u; g_cnt_h = 0u; }
    }
    grid_sync();

    // phase-B per-thread constants
    const int j4 = tid * 4;
    float4 lw[4], lb[4];
    #pragma unroll
    for (int s = 0; s < 4; s++) {
        lw[s] = *(const float4*)(lngw + s * 1024 + j4);
        lb[s] = *(const float4*)(lngb + s * 1024 + j4);
    }
    float4 cw = *(const float4*)(lncw + j4);
    float4 cb = *(const float4*)(lncb + j4);

    // per-lane ldmatrix bases for h B-fragments (2 nt-pairs x hi/lo)
    const uint32_t hrow = (uint32_t)(((lane >> 4) & 1) * 8 + (lane & 7));
    const uint32_t hkoff = (uint32_t)(((lane >> 3) & 1) * 16);
    const uint32_t lmH0 = sbase + hrow * 528u + hkoff;              // pair 0, hi
    const uint32_t lmH1 = sbase + (16u + hrow) * 528u + hkoff;      // pair 1, hi
    const uint32_t lmL0 = lmH0 + 16896u;                            // lo
    const uint32_t lmL1 = lmH1 + 16896u;

    for (int t = 0; t < TSEQ; ++t) {
        // ---- gx prefetch for phase B (independent of h; issue before h-wait) ----
        if (bid < BATCH) {
            const char* src = (const char*)(gx + ((size_t)bid * TSEQ + t) * G4);
            #pragma unroll
            for (int i = 0; i < 4; i++)
                cp16(sbase + 33792u + (uint32_t)(tid * 16 + i * 4096),
                     src + tid * 16 + i * 4096);
            cp_commit();
        }

        // ---- wait for h(t) publishers; also orders prior-step smem reads ----
        wait_counter(&g_cnt_h, 32u * (unsigned)t);

        // ---- stage h slice (32 r x 256 K, hi+lo) ----
        #pragma unroll
        for (int i = 0; i < 4; i++) {
            int e = tid + i * NTHR;             // 0..1023 uint4
            int row = e >> 5, c8 = (e & 31) * 8;
            *reinterpret_cast<uint4*>(&hsm[row * 264 + c8]) =
                *reinterpret_cast<const uint4*>(&g_hh[row * HDIM + kb + c8]);
            *reinterpret_cast<uint4*>(&hsm[8448 + row * 264 + c8]) =
                *reinterpret_cast<const uint4*>(&g_hl[row * HDIM + kb + c8]);
        }
        __syncthreads();

        // ---- 3-pass MMA over block-K slice (pass-major: no same-acc chains) ----
        float acc[4][4] = {};
        #pragma unroll
        for (int kq = 0; kq < 16; kq++) {
            uint32_t ka = (uint32_t)(kq * 32);
            uint32_t bh[8], bl[8];
            ldmx4(bh,     lmH0 + ka);
            ldmx4(bh + 4, lmH1 + ka);
            ldmx4(bl,     lmL0 + ka);
            ldmx4(bl + 4, lmL1 + ka);
            #pragma unroll
            for (int nt = 0; nt < 4; nt++)
                mma16816(acc[nt], afrh[kq], bh[2 * nt], bh[2 * nt + 1]);
            #pragma unroll
            for (int nt = 0; nt < 4; nt++)
                mma16816(acc[nt], afrh[kq], bl[2 * nt], bl[2 * nt + 1]);
            #pragma unroll
            for (int nt = 0; nt < 4; nt++)
                mma16816(acc[nt], afrl[kq], bh[2 * nt], bh[2 * nt + 1]);
        }

        // ---- store partials: g_ghp[ks4][r][j], then arrive ----
        #pragma unroll
        for (int nt = 0; nt < 4; nt++)
            #pragma unroll
            for (int c = 0; c < 4; c++) {
                int jl = wid * 16 + ((c >> 1) << 3) + (lane >> 2);
                int r = nt * 8 + ((lane & 3) << 1) + (c & 1);
                g_ghp[(size_t)(ks4 * 32 + r) * G4 + jb + jl] = acc[nt][c];
            }
        arrive_counter(&g_cnt_p);

        // ---- phase B: blocks 0..31, one batch row each ----
        if (bid < BATCH) {
            wait_counter(&g_cnt_p, 128u * (unsigned)(t + 1));
            cp_wait0();
            const int r = bid;
            float v[4][4];
            float s = 0.0f, s2 = 0.0f;
            #pragma unroll
            for (int sec = 0; sec < 4; sec++) {
                size_t off = (size_t)r * G4 + sec * 1024 + j4;
                float4 a0 = *(const float4*)&g_ghp[off];
                float4 a1 = *(const float4*)&g_ghp[off + 32ULL * G4];
                float4 a2 = *(const float4*)&g_ghp[off + 64ULL * G4];
                float4 a3 = *(const float4*)&g_ghp[off + 96ULL * G4];
                float4 xv = *(const float4*)(sgx + sec * 1024 + j4);
                float gh0 = a0.x + a1.x + a2.x + a3.x;
                float gh1 = a0.y + a1.y + a2.y + a3.y;
                float gh2 = a0.z + a1.z + a2.z + a3.z;
                float gh3 = a0.w + a1.w + a2.w + a3.w;
                v[sec][0] = xv.x + gh0 + xv.x * gh0;
                v[sec][1] = xv.y + gh1 + xv.y * gh1;
                v[sec][2] = xv.z + gh2 + xv.z * gh2;
                v[sec][3] = xv.w + gh3 + xv.w * gh3;
                #pragma unroll
                for (int q = 0; q < 4; q++) { s += v[sec][q]; s2 += v[sec][q] * v[sec][q]; }
            }
            float2 tot = reduce2(s, s2);
            float mean = tot.x * (1.0f / G4);
            float var  = tot.y * (1.0f / G4) - mean * mean;
            float rstd = rsqrtf(var + 1e-5f);

            float4 cprev = *(const float4*)(g_c + r * HDIM + j4);
            const float* pcp = &cprev.x;
            float ov[4], cv[4];
            float cs = 0.0f, cs2 = 0.0f;
            #pragma unroll
            for (int q = 0; q < 4; q++) {
                const float* pw0 = &lw[0].x; const float* pb0 = &lb[0].x;
                const float* pw1 = &lw[1].x; const float* pb1 = &lb[1].x;
                const float* pw2 = &lw[2].x; const float* pb2 = &lb[2].x;
                const float* pw3 = &lw[3].x; const float* pb3 = &lb[3].x;
                float gi = (v[0][q] - mean) * rstd * pw0[q] + pb0[q];
                float gf = (v[1][q] - mean) * rstd * pw1[q] + pb1[q];
                float gg = (v[2][q] - mean) * rstd * pw2[q] + pb2[q];
                float go = (v[3][q] - mean) * rstd * pw3[q] + pb3[q];
                float ivv = sigmoidf_(gi);
                float fvv = sigmoidf_(gf);
                float gvv = ftanh(gg);
                ov[q] = sigmoidf_(go);
                float c = fvv * pcp[q] + ivv * gvv;
                cv[q] = c;
                cs += c; cs2 += c * c;
            }
            float2 ct = reduce2(cs, cs2);
            float cm   = ct.x * (1.0f / HDIM);
            float cvar = ct.y * (1.0f / HDIM) - cm * cm;
            float crs  = rsqrtf(cvar + 1e-5f);
            const float* pcw = &cw.x; const float* pcb = &cb.x;
            float4 cno, hno;
            float* pcn = &cno.x; float* phn = &hno.x;
            #pragma unroll
            for (int q = 0; q < 4; q++) {
                float cn = (cv[q] - cm) * crs * pcw[q] + pcb[q];
                pcn[q] = cn;
                phn[q] = ov[q] * ftanh(cn);
            }
            *(float4*)(g_c + r * HDIM + j4) = cno;
            __half hh0 = __float2half_rn(hno.x);
            __half hh1 = __float2half_rn(hno.y);
            __half hh2 = __float2half_rn(hno.z);
            __half hh3 = __float2half_rn(hno.w);
            __half hl0 = __float2half_rn(hno.x - __half2float(hh0));
            __half hl1 = __float2half_rn(hno.y - __half2float(hh1));
            __half hl2 = __float2half_rn(hno.z - __half2float(hh2));
            __half hl3 = __float2half_rn(hno.w - __half2float(hh3));
            *reinterpret_cast<__half2*>(g_hh + r * HDIM + j4)     = __halves2half2(hh0, hh1);
            *reinterpret_cast<__half2*>(g_hh + r * HDIM + j4 + 2) = __halves2half2(hh2, hh3);
            *reinterpret_cast<__half2*>(g_hl + r * HDIM + j4)     = __halves2half2(hl0, hl1);
            *reinterpret_cast<__half2*>(g_hl + r * HDIM + j4 + 2) = __halves2half2(hl2, hl3);
            size_t obase = ((size_t)r * TSEQ + t) * HDIM + j4;
            if (out) {
                *(float4*)(out + obase) = hno;
            } else {
                *reinterpret_cast<__half2*>(outh + obase)     = __halves2half2(hh0, hh1);
                *reinterpret_cast<__half2*>(outh + obase + 2) = __halves2half2(hh2, hh3);
                *reinterpret_cast<__half2*>(outl + obase)     = __halves2half2(hl0, hl1);
                *reinterpret_cast<__half2*>(outl + obase + 2) = __halves2half2(hl2, hl3);
            }
            arrive_counter(&g_cnt_h);
        }
    }
}

// ---------------- launch ----------------
extern "C" void kernel_launch(void* const* d_in, const int* in_sizes, int n_in,
                              void* d_out, int out_size) {
    const float* x    = (const float*)d_in[0];
    const float* W    = (const float*)d_in[1];
    const float* b    = (const float*)d_in[2];
    const float* U    = (const float*)d_in[3];
    const float* lngw = (const float*)d_in[4];
    const float* lngb = (const float*)d_in[5];
    const float* lncw = (const float*)d_in[6];
    const float* lncb = (const float*)d_in[7];
    float* y = (float*)d_out;

    cudaFuncSetAttribute(milstm_mma, cudaFuncAttributeMaxDynamicSharedMemorySize,
                         SMEM_DYN);
    cudaFuncSetAttribute(sgemm_hmma, cudaFuncAttributeMaxDynamicSharedMemorySize,
                         SMEM_GEMM);

    float *gx;
    cudaGetSymbolAddress((void**)&gx, g_gx);
    __half *Uh, *Ul, *Wh, *Wl, *Ah, *Al;
    cudaGetSymbolAddress((void**)&Uh, g_Uh);
    cudaGetSymbolAddress((void**)&Ul, g_Ul);
    cudaGetSymbolAddress((void**)&Wh, g_Wh);
    cudaGetSymbolAddress((void**)&Wl, g_Wl);
    cudaGetSymbolAddress((void**)&Ah, g_Ah);
    cudaGetSymbolAddress((void**)&Al, g_Al);

    const size_t WSZ = 2ULL * G4 * HDIM;
    const size_t ASZ = (size_t)BATCH * TSEQ * HDIM;
    const size_t LOFF = (size_t)G4 * HDIM;

    pack_hilo<<<1024, 256>>>(U, Uh, Ul, WSZ);
    pack_hilo<<<1024, 256>>>(W, Wh, Wl, WSZ);
    pack_hilo<<<1024, 256>>>(x, Ah, Al, ASZ);

    dim3 gg(G4 / 128, BATCH * TSEQ / 128);   // (32, 128)

    // layer 0 (h written straight to Ah/Al in sgemm A-layout)
    sgemm_hmma<<<gg, 256, SMEM_GEMM>>>(Ah, Al, Wh, Wl, b, gx);
    milstm_mma<<<NBLK, NTHR, SMEM_DYN>>>(gx, Uh, Ul, lngw, lngb, lncw, lncb,
                                         nullptr, Ah, Al);
    // layer 1
    sgemm_hmma<<<gg, 256, SMEM_GEMM>>>(Ah, Al, Wh + LOFF, Wl + LOFF, b + G4, gx);
    milstm_mma<<<NBLK, NTHR, SMEM_DYN>>>(gx, Uh + LOFF, Ul + LOFF,
                                         lngw + G4, lngb + G4,
                                         lncw + HDIM, lncb + HDIM, y,
                                         nullptr, nullptr);
}